// round 13
// baseline (speedup 1.0000x reference)
#include <cuda_runtime.h>
#include <cuda_fp16.h>
#include <cstdint>

#define MAX_N 100000
#define MAX_E 1600000
#define F 128
#define SCAN_CHUNK 512
#define MAX_BLK ((MAX_N + SCAN_CHUNK - 1) / SCAN_CHUNK)
#define PITCH 132   // 128 + 4 pad: conflict-free mma A-frag loads

// Scratch (__device__ globals; no allocations allowed)
__device__ __half2 g_h16[(size_t)MAX_N * (F / 2)];  // x@W (UNscaled), fp16
__device__ float g_dinv[MAX_N];
__device__ int   g_cnt[MAX_N];
__device__ int   g_start[MAX_N];
__device__ int   g_cursor[MAX_N];
__device__ int   g_esrc[MAX_E];
__device__ int   g_bsum[MAX_BLK];
__device__ float4 g_wfrag[16 * 8 * 32];     // frag-ordered tf32 W (64KB)

// ---------------------------------------------------------------------------
__global__ void k_zero(int n) {
    int i = blockIdx.x * blockDim.x + threadIdx.x;
    if (i < n) g_cnt[i] = 0;
}

__global__ void k_hist(const int* __restrict__ dst, int e) {
    int i = blockIdx.x * blockDim.x + threadIdx.x;
    if (i < e) atomicAdd(&g_cnt[dst[i]], 1);
}

__global__ void k_scan1(int n) {
    __shared__ int wsum[16];
    int b = blockIdx.x;
    int i = b * SCAN_CHUNK + threadIdx.x;
    int v = (i < n) ? g_cnt[i] : 0;
    for (int o = 16; o > 0; o >>= 1) v += __shfl_down_sync(~0u, v, o);
    int lane = threadIdx.x & 31, wid = threadIdx.x >> 5;
    if (lane == 0) wsum[wid] = v;
    __syncthreads();
    if (wid == 0) {
        int s = (lane < (SCAN_CHUNK / 32)) ? wsum[lane] : 0;
        for (int o = 16; o > 0; o >>= 1) s += __shfl_down_sync(~0u, s, o);
        if (lane == 0) g_bsum[b] = s;
    }
}

// fused: every block re-scans all block sums locally, then does its own chunk.
// Also computes g_dinv.
__global__ void k_scan3(int n, int nblk) {
    __shared__ int wsum[16];
    __shared__ int sh_off;
    int b = blockIdx.x;
    int t = threadIdx.x;
    int lane = t & 31, wid = t >> 5;

    {
        int v = (t < nblk) ? g_bsum[t] : 0;
        int x = v;
        for (int o = 1; o < 32; o <<= 1) {
            int y = __shfl_up_sync(~0u, x, o);
            if (lane >= o) x += y;
        }
        if (lane == 31) wsum[wid] = x;
        __syncthreads();
        if (wid == 0) {
            int w = (lane < 16) ? wsum[lane] : 0;
            for (int o = 1; o < 16; o <<= 1) {
                int y = __shfl_up_sync(~0u, w, o);
                if (lane >= o) w += y;
            }
            if (lane < 16) wsum[lane] = w;
        }
        __syncthreads();
        int excl = x - v + (wid ? wsum[wid - 1] : 0);
        if (t == b) sh_off = excl;
        __syncthreads();
    }

    int i = b * SCAN_CHUNK + t;
    int v = (i < n) ? g_cnt[i] : 0;
    int x = v;
    for (int o = 1; o < 32; o <<= 1) {
        int y = __shfl_up_sync(~0u, x, o);
        if (lane >= o) x += y;
    }
    if (lane == 31) wsum[wid] = x;
    __syncthreads();
    if (wid == 0) {
        int w = (lane < 16) ? wsum[lane] : 0;
        for (int o = 1; o < 16; o <<= 1) {
            int y = __shfl_up_sync(~0u, w, o);
            if (lane >= o) w += y;
        }
        if (lane < 16) wsum[lane] = w;
    }
    __syncthreads();
    int excl = x - v + (wid ? wsum[wid - 1] : 0);
    if (i < n) {
        int s = excl + sh_off;
        g_start[i] = s;
        g_cursor[i] = s;
        g_dinv[i] = rsqrtf((float)(v + 1));
    }
}

__global__ void k_fill(const int* __restrict__ src, const int* __restrict__ dst,
                       int e) {
    int i = blockIdx.x * blockDim.x + threadIdx.x;
    if (i < e) {
        int p = atomicAdd(&g_cursor[dst[i]], 1);
        g_esrc[p] = src[i];
    }
}

// ---------------------------------------------------------------------------
__device__ __forceinline__ unsigned cvt_tf32(float f) {
    unsigned u;
    asm("cvt.rna.tf32.f32 %0, %1;" : "=r"(u) : "f"(f));
    return u;
}

// One-time: convert W into fragment-ordered tf32.
__global__ void k_wprep(const float* __restrict__ W) {
    int i = blockIdx.x * blockDim.x + threadIdx.x;
    if (i >= 16 * 8 * 32) return;
    int lane = i & 31;
    int ktp = (i >> 5) & 7;
    int nt = i >> 8;
    int g = lane >> 2, t = lane & 3;
    int nc = nt * 8 + g;
    int k0 = ktp * 16 + t;
    float4 o;
    o.x = __uint_as_float(cvt_tf32(W[(k0)      * F + nc]));
    o.y = __uint_as_float(cvt_tf32(W[(k0 + 4)  * F + nc]));
    o.z = __uint_as_float(cvt_tf32(W[(k0 + 8)  * F + nc]));
    o.w = __uint_as_float(cvt_tf32(W[(k0 + 12) * F + nc]));
    g_wfrag[i] = o;
}

// GEMM via HMMA tf32: g_h16 = x @ W (UNscaled), fp16 out. Fully independent
// of the edge inputs -> runs from t=0 parallel to the whole CSR build.
__global__ __launch_bounds__(256, 2) void k_gemm(const float* __restrict__ x,
                                                 int n) {
    extern __shared__ float xs[];     // xs[r*PITCH + k] = tf32(x[row0+r][k])

    const int tid = threadIdx.x;
    const int row0 = blockIdx.x * 128;
    for (int i = tid; i < 128 * 32; i += 256) {
        int r = i >> 5, k4 = i & 31;
        float4 v = make_float4(0.f, 0.f, 0.f, 0.f);
        if (row0 + r < n) v = ((const float4*)x)[(long long)(row0 + r) * 32 + k4];
        v.x = __uint_as_float(cvt_tf32(v.x));
        v.y = __uint_as_float(cvt_tf32(v.y));
        v.z = __uint_as_float(cvt_tf32(v.z));
        v.w = __uint_as_float(cvt_tf32(v.w));
        *(float4*)&xs[r * PITCH + k4 * 4] = v;
    }
    __syncthreads();

    const int warp = tid >> 5, lane = tid & 31;
    const int g = lane >> 2, t = lane & 3;
    const int rbase = warp * 16;

    unsigned a[16][4];
#pragma unroll
    for (int kt = 0; kt < 16; kt++) {
        a[kt][0] = __float_as_uint(xs[(rbase + g) * PITCH + kt * 8 + t]);
        a[kt][1] = __float_as_uint(xs[(rbase + g + 8) * PITCH + kt * 8 + t]);
        a[kt][2] = __float_as_uint(xs[(rbase + g) * PITCH + kt * 8 + t + 4]);
        a[kt][3] = __float_as_uint(xs[(rbase + g + 8) * PITCH + kt * 8 + t + 4]);
    }

    const int row_g = row0 + rbase + g;

    const float4* wf = g_wfrag;
#pragma unroll 4
    for (int nt = 0; nt < 16; nt++) {
        float d0 = 0.f, d1 = 0.f, d2 = 0.f, d3 = 0.f;
#pragma unroll
        for (int ktp = 0; ktp < 8; ktp++) {
            float4 bf = wf[(nt * 8 + ktp) * 32 + lane];
            asm volatile(
                "mma.sync.aligned.m16n8k8.row.col.f32.tf32.tf32.f32 "
                "{%0,%1,%2,%3}, {%4,%5,%6,%7}, {%8,%9}, {%0,%1,%2,%3};"
                : "+f"(d0), "+f"(d1), "+f"(d2), "+f"(d3)
                : "r"(a[2 * ktp][0]), "r"(a[2 * ktp][1]),
                  "r"(a[2 * ktp][2]), "r"(a[2 * ktp][3]),
                  "r"(__float_as_uint(bf.x)), "r"(__float_as_uint(bf.y)));
            asm volatile(
                "mma.sync.aligned.m16n8k8.row.col.f32.tf32.tf32.f32 "
                "{%0,%1,%2,%3}, {%4,%5,%6,%7}, {%8,%9}, {%0,%1,%2,%3};"
                : "+f"(d0), "+f"(d1), "+f"(d2), "+f"(d3)
                : "r"(a[2 * ktp + 1][0]), "r"(a[2 * ktp + 1][1]),
                  "r"(a[2 * ktp + 1][2]), "r"(a[2 * ktp + 1][3]),
                  "r"(__float_as_uint(bf.z)), "r"(__float_as_uint(bf.w)));
        }
        if (row_g < n)
            g_h16[(size_t)row_g * 64 + nt * 4 + t] = __floats2half2_rn(d0, d1);
        if (row_g + 8 < n)
            g_h16[(size_t)(row_g + 8) * 64 + nt * 4 + t] = __floats2half2_rn(d2, d3);
    }
}

// ---------------------------------------------------------------------------
// Aggregate: one warp per dst node; uint2/lane fp16 gathers (256B rows),
// per-edge scale dinv[s] (broadcast load), fp32 FMA accumulation, unroll 8.
__global__ __launch_bounds__(256) void k_agg(const float* __restrict__ bias,
                                             float* __restrict__ out, int n) {
    int node = blockIdx.x * 8 + (threadIdx.x >> 5);
    if (node >= n) return;
    int lane = threadIdx.x & 31;

    const uint2* h = (const uint2*)g_h16;  // 4 halfs / lane / row
    float dd = g_dinv[node];

    float4 acc;
    {
        uint2 sv = h[(size_t)node * 32 + lane];  // self-loop message * dinv[node]
        float2 f0 = __half22float2(*(__half2*)&sv.x);
        float2 f1 = __half22float2(*(__half2*)&sv.y);
        acc.x = f0.x * dd; acc.y = f0.y * dd;
        acc.z = f1.x * dd; acc.w = f1.y * dd;
    }

    int j = g_start[node];
    int end = j + g_cnt[node];

    for (; j + 7 < end; j += 8) {
        int s0 = g_esrc[j],     s1 = g_esrc[j + 1];
        int s2 = g_esrc[j + 2], s3 = g_esrc[j + 3];
        int s4 = g_esrc[j + 4], s5 = g_esrc[j + 5];
        int s6 = g_esrc[j + 6], s7 = g_esrc[j + 7];
        uint2 v0 = h[(size_t)s0 * 32 + lane];
        uint2 v1 = h[(size_t)s1 * 32 + lane];
        uint2 v2 = h[(size_t)s2 * 32 + lane];
        uint2 v3 = h[(size_t)s3 * 32 + lane];
        uint2 v4 = h[(size_t)s4 * 32 + lane];
        uint2 v5 = h[(size_t)s5 * 32 + lane];
        uint2 v6 = h[(size_t)s6 * 32 + lane];
        uint2 v7 = h[(size_t)s7 * 32 + lane];
        float c0 = g_dinv[s0], c1 = g_dinv[s1], c2 = g_dinv[s2], c3 = g_dinv[s3];
        float c4 = g_dinv[s4], c5 = g_dinv[s5], c6 = g_dinv[s6], c7 = g_dinv[s7];
#pragma unroll
        for (int k = 0; k < 8; k++) {
            uint2 v = (k == 0) ? v0 : (k == 1) ? v1 : (k == 2) ? v2 :
                      (k == 3) ? v3 : (k == 4) ? v4 : (k == 5) ? v5 :
                      (k == 6) ? v6 : v7;
            float c = (k == 0) ? c0 : (k == 1) ? c1 : (k == 2) ? c2 :
                      (k == 3) ? c3 : (k == 4) ? c4 : (k == 5) ? c5 :
                      (k == 6) ? c6 : c7;
            float2 f0 = __half22float2(*(__half2*)&v.x);
            float2 f1 = __half22float2(*(__half2*)&v.y);
            acc.x += f0.x * c; acc.y += f0.y * c;
            acc.z += f1.x * c; acc.w += f1.y * c;
        }
    }
    for (; j < end; j++) {
        int s = g_esrc[j];
        uint2 v = h[(size_t)s * 32 + lane];
        float c = g_dinv[s];
        float2 f0 = __half22float2(*(__half2*)&v.x);
        float2 f1 = __half22float2(*(__half2*)&v.y);
        acc.x += f0.x * c; acc.y += f0.y * c;
        acc.z += f1.x * c; acc.w += f1.y * c;
    }

    float4 bv = ((const float4*)bias)[lane];
    float4 o;
    o.x = acc.x * dd + bv.x;
    o.y = acc.y * dd + bv.y;
    o.z = acc.z * dd + bv.z;
    o.w = acc.w * dd + bv.w;
    ((float4*)out)[(size_t)node * 32 + lane] = o;
}

// ---------------------------------------------------------------------------
// Launch DAG:
//   [B: wprep -> gemm]                         (side stream, starts at t=0)
//   [A: zero -> hist -> scan1 -> scan3 -> fill] (main stream, ~26us, hidden)
//   join(A, B) -> agg
extern "C" void kernel_launch(void* const* d_in, const int* in_sizes, int n_in,
                              void* d_out, int out_size) {
    const float* x  = (const float*)d_in[0];
    const int*   ei = (const int*)d_in[1];
    const float* W  = (const float*)d_in[3];
    const float* b  = (const float*)d_in[4];
    float* out = (float*)d_out;

    int n = in_sizes[0] / F;
    int e = in_sizes[1] / 2;
    const int* src = ei;
    const int* dst = ei + e;

    int nblk = (n + SCAN_CHUNK - 1) / SCAN_CHUNK;
    int smem = 128 * PITCH * (int)sizeof(float);   // 67.6 KB

    // One-time host-side setup on the (uncaptured) correctness call.
    static cudaStream_t s2 = nullptr;
    static cudaEvent_t evGemm = nullptr;
    if (s2 == nullptr) {
        cudaFuncSetAttribute(k_gemm, cudaFuncAttributeMaxDynamicSharedMemorySize,
                             smem);
        cudaStreamCreateWithFlags(&s2, cudaStreamNonBlocking);
        cudaEventCreateWithFlags(&evGemm, cudaEventDisableTiming);
    }

    // Graph capture on stream 0 forks to s2; s2 chain has no upstream deps,
    // so in the captured graph it is a root chain running parallel to A.
    // (Fork is established by having s2 wait on an event recorded at capture
    // start on stream 0 — use a zero-work marker.)
    static cudaEvent_t evRoot = nullptr;
    if (evRoot == nullptr)
        cudaEventCreateWithFlags(&evRoot, cudaEventDisableTiming);
    cudaEventRecord(evRoot, 0);
    cudaStreamWaitEvent(s2, evRoot, 0);

    // dense chain (independent of edges)
    k_wprep<<<16, 256, 0, s2>>>(W);
    k_gemm <<<(n + 127) / 128, 256, smem, s2>>>(x, n);
    cudaEventRecord(evGemm, s2);

    // edge/CSR chain
    k_zero <<<(n + 255) / 256, 256>>>(n);
    k_hist <<<(e + 255) / 256, 256>>>(dst, e);
    k_scan1<<<nblk, SCAN_CHUNK>>>(n);
    k_scan3<<<nblk, SCAN_CHUNK>>>(n, nblk);
    k_fill <<<(e + 255) / 256, 256>>>(src, dst, e);

    // join
    cudaStreamWaitEvent(0, evGemm, 0);
    k_agg  <<<(n + 7) / 8, 256>>>(b, out, n);
}

// round 14
// speedup vs baseline: 1.2205x; 1.2205x over previous
#include <cuda_runtime.h>
#include <cuda_fp16.h>
#include <cstdint>

#define MAX_N 100000
#define MAX_E 1600000
#define F 128
#define SCAN_CHUNK 512
#define MAX_BLK ((MAX_N + SCAN_CHUNK - 1) / SCAN_CHUNK)
#define P2 68    // half2 pitch per row (64 + 4 pad): conflict-free frag LDS

// Scratch (__device__ globals; no allocations allowed)
__device__ __half2 g_h16[(size_t)MAX_N * (F / 2)];  // (x@W)*dinv[row], fp16
__device__ float g_dinv[MAX_N];
__device__ int   g_cnt[MAX_N];
__device__ int   g_start[MAX_N];
__device__ int   g_cursor[MAX_N];
__device__ int   g_esrc[MAX_E];
__device__ int   g_bsum[MAX_BLK];
__device__ uint4 g_wf16[16 * 4 * 32];     // frag-ordered fp16 W (32KB)

// ---------------------------------------------------------------------------
__global__ void k_zero(int n) {
    int i = blockIdx.x * blockDim.x + threadIdx.x;
    if (i < n) g_cnt[i] = 0;
}

__global__ void k_hist(const int* __restrict__ dst, int e) {
    int i = blockIdx.x * blockDim.x + threadIdx.x;
    if (i < e) atomicAdd(&g_cnt[dst[i]], 1);
}

__global__ void k_scan1(int n) {
    __shared__ int wsum[16];
    int b = blockIdx.x;
    int i = b * SCAN_CHUNK + threadIdx.x;
    int v = (i < n) ? g_cnt[i] : 0;
    for (int o = 16; o > 0; o >>= 1) v += __shfl_down_sync(~0u, v, o);
    int lane = threadIdx.x & 31, wid = threadIdx.x >> 5;
    if (lane == 0) wsum[wid] = v;
    __syncthreads();
    if (wid == 0) {
        int s = (lane < (SCAN_CHUNK / 32)) ? wsum[lane] : 0;
        for (int o = 16; o > 0; o >>= 1) s += __shfl_down_sync(~0u, s, o);
        if (lane == 0) g_bsum[b] = s;
    }
}

// fused: every block re-scans all block sums locally, then does its own chunk
__global__ void k_scan3(int n, int nblk) {
    __shared__ int wsum[16];
    __shared__ int sh_off;
    int b = blockIdx.x;
    int t = threadIdx.x;
    int lane = t & 31, wid = t >> 5;

    {
        int v = (t < nblk) ? g_bsum[t] : 0;
        int x = v;
        for (int o = 1; o < 32; o <<= 1) {
            int y = __shfl_up_sync(~0u, x, o);
            if (lane >= o) x += y;
        }
        if (lane == 31) wsum[wid] = x;
        __syncthreads();
        if (wid == 0) {
            int w = (lane < 16) ? wsum[lane] : 0;
            for (int o = 1; o < 16; o <<= 1) {
                int y = __shfl_up_sync(~0u, w, o);
                if (lane >= o) w += y;
            }
            if (lane < 16) wsum[lane] = w;
        }
        __syncthreads();
        int excl = x - v + (wid ? wsum[wid - 1] : 0);
        if (t == b) sh_off = excl;
        __syncthreads();
    }

    int i = b * SCAN_CHUNK + t;
    int v = (i < n) ? g_cnt[i] : 0;
    int x = v;
    for (int o = 1; o < 32; o <<= 1) {
        int y = __shfl_up_sync(~0u, x, o);
        if (lane >= o) x += y;
    }
    if (lane == 31) wsum[wid] = x;
    __syncthreads();
    if (wid == 0) {
        int w = (lane < 16) ? wsum[lane] : 0;
        for (int o = 1; o < 16; o <<= 1) {
            int y = __shfl_up_sync(~0u, w, o);
            if (lane >= o) w += y;
        }
        if (lane < 16) wsum[lane] = w;
    }
    __syncthreads();
    int excl = x - v + (wid ? wsum[wid - 1] : 0);
    if (i < n) {
        int s = excl + sh_off;
        g_start[i] = s;
        g_cursor[i] = s;
    }
}

__global__ void k_fill(const int* __restrict__ src, const int* __restrict__ dst,
                       int e) {
    int i = blockIdx.x * blockDim.x + threadIdx.x;
    if (i < e) {
        int p = atomicAdd(&g_cursor[dst[i]], 1);
        g_esrc[p] = src[i];
    }
}

// ---------------------------------------------------------------------------
__device__ __forceinline__ unsigned pack_h2(float f0, float f1) {
    __half2 h = __floats2half2_rn(f0, f1);
    return *(unsigned*)&h;
}

// One-time: convert W into m16n8k16 fp16 B-fragment order.
// i: lane = i&31, ktp = (i>>5)&3, nt = i>>7.  kt = 2*ktp, 2*ktp+1.
// uint4 = { b0(kt), b1(kt), b0(kt+1), b1(kt+1) } for thread (g = lane>>2, t = lane&3):
//   b0(kt): half2( W[kt*16 + 2t][nc], W[kt*16 + 2t + 1][nc] ),  nc = nt*8+g
//   b1(kt): half2( W[kt*16 + 8 + 2t][nc], W[kt*16 + 9 + 2t][nc] )
__global__ void k_wprep(const float* __restrict__ W) {
    int i = blockIdx.x * blockDim.x + threadIdx.x;
    if (i >= 16 * 4 * 32) return;
    int lane = i & 31;
    int ktp = (i >> 5) & 3;
    int nt = i >> 7;
    int g = lane >> 2, t = lane & 3;
    int nc = nt * 8 + g;
    int k0 = ktp * 32 + 2 * t;          // kt = 2*ktp  -> k base ktp*32
    uint4 o;
    o.x = pack_h2(W[(k0)      * F + nc], W[(k0 + 1)  * F + nc]);
    o.y = pack_h2(W[(k0 + 8)  * F + nc], W[(k0 + 9)  * F + nc]);
    o.z = pack_h2(W[(k0 + 16) * F + nc], W[(k0 + 17) * F + nc]);
    o.w = pack_h2(W[(k0 + 24) * F + nc], W[(k0 + 25) * F + nc]);
    g_wf16[i] = o;
}

// GEMM via HMMA fp16 (m16n8k16): g_h16 = (x @ W) * dinv[row], fp16 out.
// B frags streamed from g_wf16 (broadcast LDG.128). 34KB static smem,
// ~80 regs -> 3 CTAs/SM target.
__global__ __launch_bounds__(256, 3) void k_gemm(const float* __restrict__ x,
                                                 int n) {
    __shared__ unsigned xs2[128 * P2];   // half2 bits, row pitch P2

    const int tid = threadIdx.x;
    const int row0 = blockIdx.x * 128;
    for (int i = tid; i < 128 * 32; i += 256) {
        int r = i >> 5, k4 = i & 31;
        float4 v = make_float4(0.f, 0.f, 0.f, 0.f);
        if (row0 + r < n) v = ((const float4*)x)[(long long)(row0 + r) * 32 + k4];
        xs2[r * P2 + k4 * 2]     = pack_h2(v.x, v.y);
        xs2[r * P2 + k4 * 2 + 1] = pack_h2(v.z, v.w);
    }
    // dinv for this block's rows
    if (tid < 128 && row0 + tid < n)
        g_dinv[row0 + tid] = rsqrtf((float)(g_cnt[row0 + tid] + 1));
    __syncthreads();

    const int warp = tid >> 5, lane = tid & 31;
    const int g = lane >> 2, t = lane & 3;
    const int rbase = warp * 16;

    // A frags: 8 k-tiles (k16 each) x 4 regs (half2 each)
    unsigned a[8][4];
#pragma unroll
    for (int kt = 0; kt < 8; kt++) {
        int base = kt * 8;
        a[kt][0] = xs2[(rbase + g)     * P2 + base + t];
        a[kt][1] = xs2[(rbase + g + 8) * P2 + base + t];
        a[kt][2] = xs2[(rbase + g)     * P2 + base + t + 4];
        a[kt][3] = xs2[(rbase + g + 8) * P2 + base + t + 4];
    }

    const int row_g = row0 + rbase + g;
    float sr  = (row_g < n)     ? rsqrtf((float)(g_cnt[row_g] + 1))     : 0.f;
    float sr8 = (row_g + 8 < n) ? rsqrtf((float)(g_cnt[row_g + 8] + 1)) : 0.f;

    const uint4* wf = g_wf16;
#pragma unroll 4
    for (int nt = 0; nt < 16; nt++) {
        float d0 = 0.f, d1 = 0.f, d2 = 0.f, d3 = 0.f;
#pragma unroll
        for (int ktp = 0; ktp < 4; ktp++) {
            uint4 bf = wf[(nt * 4 + ktp) * 32 + lane];
            asm volatile(
                "mma.sync.aligned.m16n8k16.row.col.f32.f16.f16.f32 "
                "{%0,%1,%2,%3}, {%4,%5,%6,%7}, {%8,%9}, {%0,%1,%2,%3};"
                : "+f"(d0), "+f"(d1), "+f"(d2), "+f"(d3)
                : "r"(a[2 * ktp][0]), "r"(a[2 * ktp][1]),
                  "r"(a[2 * ktp][2]), "r"(a[2 * ktp][3]),
                  "r"(bf.x), "r"(bf.y));
            asm volatile(
                "mma.sync.aligned.m16n8k16.row.col.f32.f16.f16.f32 "
                "{%0,%1,%2,%3}, {%4,%5,%6,%7}, {%8,%9}, {%0,%1,%2,%3};"
                : "+f"(d0), "+f"(d1), "+f"(d2), "+f"(d3)
                : "r"(a[2 * ktp + 1][0]), "r"(a[2 * ktp + 1][1]),
                  "r"(a[2 * ktp + 1][2]), "r"(a[2 * ktp + 1][3]),
                  "r"(bf.z), "r"(bf.w));
        }
        if (row_g < n)
            g_h16[(size_t)row_g * 64 + nt * 4 + t] =
                __floats2half2_rn(d0 * sr, d1 * sr);
        if (row_g + 8 < n)
            g_h16[(size_t)(row_g + 8) * 64 + nt * 4 + t] =
                __floats2half2_rn(d2 * sr8, d3 * sr8);
    }
}

// ---------------------------------------------------------------------------
// Aggregate: one warp per dst node; uint2/lane fp16 gathers (256B rows),
// fp32 accumulation, 8 independent gathers in flight per iteration.
__global__ __launch_bounds__(256) void k_agg(const float* __restrict__ bias,
                                             float* __restrict__ out, int n) {
    int node = blockIdx.x * 8 + (threadIdx.x >> 5);
    if (node >= n) return;
    int lane = threadIdx.x & 31;

    const uint2* h = (const uint2*)g_h16;  // 4 halfs / lane / row
    float dd = g_dinv[node];

    float4 acc;
    {
        uint2 sv = h[(size_t)node * 32 + lane];  // self-loop message
        float2 f0 = __half22float2(*(__half2*)&sv.x);
        float2 f1 = __half22float2(*(__half2*)&sv.y);
        acc.x = f0.x; acc.y = f0.y; acc.z = f1.x; acc.w = f1.y;
    }

    int j = g_start[node];
    int end = j + g_cnt[node];

    for (; j + 7 < end; j += 8) {
        int s0 = g_esrc[j],     s1 = g_esrc[j + 1];
        int s2 = g_esrc[j + 2], s3 = g_esrc[j + 3];
        int s4 = g_esrc[j + 4], s5 = g_esrc[j + 5];
        int s6 = g_esrc[j + 6], s7 = g_esrc[j + 7];
        uint2 v0 = h[(size_t)s0 * 32 + lane];
        uint2 v1 = h[(size_t)s1 * 32 + lane];
        uint2 v2 = h[(size_t)s2 * 32 + lane];
        uint2 v3 = h[(size_t)s3 * 32 + lane];
        uint2 v4 = h[(size_t)s4 * 32 + lane];
        uint2 v5 = h[(size_t)s5 * 32 + lane];
        uint2 v6 = h[(size_t)s6 * 32 + lane];
        uint2 v7 = h[(size_t)s7 * 32 + lane];
#pragma unroll
        for (int k = 0; k < 8; k++) {
            uint2 v = (k == 0) ? v0 : (k == 1) ? v1 : (k == 2) ? v2 :
                      (k == 3) ? v3 : (k == 4) ? v4 : (k == 5) ? v5 :
                      (k == 6) ? v6 : v7;
            float2 f0 = __half22float2(*(__half2*)&v.x);
            float2 f1 = __half22float2(*(__half2*)&v.y);
            acc.x += f0.x; acc.y += f0.y; acc.z += f1.x; acc.w += f1.y;
        }
    }
    for (; j + 3 < end; j += 4) {
        int s0 = g_esrc[j],     s1 = g_esrc[j + 1];
        int s2 = g_esrc[j + 2], s3 = g_esrc[j + 3];
        uint2 v0 = h[(size_t)s0 * 32 + lane];
        uint2 v1 = h[(size_t)s1 * 32 + lane];
        uint2 v2 = h[(size_t)s2 * 32 + lane];
        uint2 v3 = h[(size_t)s3 * 32 + lane];
#pragma unroll
        for (int k = 0; k < 4; k++) {
            uint2 v = (k == 0) ? v0 : (k == 1) ? v1 : (k == 2) ? v2 : v3;
            float2 f0 = __half22float2(*(__half2*)&v.x);
            float2 f1 = __half22float2(*(__half2*)&v.y);
            acc.x += f0.x; acc.y += f0.y; acc.z += f1.x; acc.w += f1.y;
        }
    }
    for (; j < end; j++) {
        int s = g_esrc[j];
        uint2 v = h[(size_t)s * 32 + lane];
        float2 f0 = __half22float2(*(__half2*)&v.x);
        float2 f1 = __half22float2(*(__half2*)&v.y);
        acc.x += f0.x; acc.y += f0.y; acc.z += f1.x; acc.w += f1.y;
    }

    float4 bv = ((const float4*)bias)[lane];
    float4 o;
    o.x = acc.x * dd + bv.x;
    o.y = acc.y * dd + bv.y;
    o.z = acc.z * dd + bv.z;
    o.w = acc.w * dd + bv.w;
    ((float4*)out)[(size_t)node * 32 + lane] = o;
}

// ---------------------------------------------------------------------------
// Launch DAG (R12 structure):
//   zero -> hist -> [A: scan1 -> scan3 -> fill]   (edge chain, hidden)
//                   [B: wprep -> gemm]            (dense chain, side stream)
//   join(A, B) -> agg
extern "C" void kernel_launch(void* const* d_in, const int* in_sizes, int n_in,
                              void* d_out, int out_size) {
    const float* x  = (const float*)d_in[0];
    const int*   ei = (const int*)d_in[1];
    const float* W  = (const float*)d_in[3];
    const float* b  = (const float*)d_in[4];
    float* out = (float*)d_out;

    int n = in_sizes[0] / F;
    int e = in_sizes[1] / 2;
    const int* src = ei;
    const int* dst = ei + e;

    int nblk = (n + SCAN_CHUNK - 1) / SCAN_CHUNK;

    // One-time host-side setup on the (uncaptured) correctness call.
    static cudaStream_t s2 = nullptr;
    static cudaEvent_t evHist = nullptr, evGemm = nullptr;
    if (s2 == nullptr) {
        cudaStreamCreateWithFlags(&s2, cudaStreamNonBlocking);
        cudaEventCreateWithFlags(&evHist, cudaEventDisableTiming);
        cudaEventCreateWithFlags(&evGemm, cudaEventDisableTiming);
    }

    k_zero <<<(n + 255) / 256, 256>>>(n);
    k_hist <<<(e + 255) / 256, 256>>>(dst, e);
    cudaEventRecord(evHist, 0);

    // dense chain on side stream (waits for hist: gemm reads g_cnt for dinv)
    cudaStreamWaitEvent(s2, evHist, 0);
    k_wprep<<<8, 256, 0, s2>>>(W);
    k_gemm <<<(n + 127) / 128, 256, 0, s2>>>(x, n);
    cudaEventRecord(evGemm, s2);

    // edge chain on main stream (overlaps with gemm)
    k_scan1<<<nblk, SCAN_CHUNK>>>(n);
    k_scan3<<<nblk, SCAN_CHUNK>>>(n, nblk);
    k_fill <<<(e + 255) / 256, 256>>>(src, dst, e);

    // join
    cudaStreamWaitEvent(0, evGemm, 0);
    k_agg  <<<(n + 7) / 8, 256>>>(b, out, n);
}

// round 15
// speedup vs baseline: 1.3212x; 1.0826x over previous
#include <cuda_runtime.h>
#include <cuda_fp16.h>
#include <cstdint>

#define MAX_N 100000
#define MAX_E 1600000
#define F 128
#define SCAN_CHUNK 512
#define MAX_BLK ((MAX_N + SCAN_CHUNK - 1) / SCAN_CHUNK)

// Scratch (__device__ globals; no allocations allowed)
__device__ __half2 g_h16[(size_t)MAX_N * (F / 2)];  // (x@W)*dinv[row], fp16
__device__ float g_dinv[MAX_N];
__device__ int   g_cnt[MAX_N];
__device__ int   g_start[MAX_N];
__device__ int   g_cursor[MAX_N];
__device__ int   g_esrc[MAX_E];
__device__ int   g_bsum[MAX_BLK];
__device__ uint4 g_wf16[16 * 4 * 32];     // frag-ordered fp16 W (32KB)

// ---------------------------------------------------------------------------
__global__ void k_zero(int n) {
    int i = blockIdx.x * blockDim.x + threadIdx.x;
    if (i < n) g_cnt[i] = 0;
}

__global__ void k_hist(const int* __restrict__ dst, int e) {
    int i = blockIdx.x * blockDim.x + threadIdx.x;
    if (i < e) atomicAdd(&g_cnt[dst[i]], 1);
}

__global__ void k_scan1(int n) {
    __shared__ int wsum[16];
    int b = blockIdx.x;
    int i = b * SCAN_CHUNK + threadIdx.x;
    int v = (i < n) ? g_cnt[i] : 0;
    for (int o = 16; o > 0; o >>= 1) v += __shfl_down_sync(~0u, v, o);
    int lane = threadIdx.x & 31, wid = threadIdx.x >> 5;
    if (lane == 0) wsum[wid] = v;
    __syncthreads();
    if (wid == 0) {
        int s = (lane < (SCAN_CHUNK / 32)) ? wsum[lane] : 0;
        for (int o = 16; o > 0; o >>= 1) s += __shfl_down_sync(~0u, s, o);
        if (lane == 0) g_bsum[b] = s;
    }
}

// fused: every block re-scans all block sums locally, then does its own chunk
__global__ void k_scan3(int n, int nblk) {
    __shared__ int wsum[16];
    __shared__ int sh_off;
    int b = blockIdx.x;
    int t = threadIdx.x;
    int lane = t & 31, wid = t >> 5;

    {
        int v = (t < nblk) ? g_bsum[t] : 0;
        int x = v;
        for (int o = 1; o < 32; o <<= 1) {
            int y = __shfl_up_sync(~0u, x, o);
            if (lane >= o) x += y;
        }
        if (lane == 31) wsum[wid] = x;
        __syncthreads();
        if (wid == 0) {
            int w = (lane < 16) ? wsum[lane] : 0;
            for (int o = 1; o < 16; o <<= 1) {
                int y = __shfl_up_sync(~0u, w, o);
                if (lane >= o) w += y;
            }
            if (lane < 16) wsum[lane] = w;
        }
        __syncthreads();
        int excl = x - v + (wid ? wsum[wid - 1] : 0);
        if (t == b) sh_off = excl;
        __syncthreads();
    }

    int i = b * SCAN_CHUNK + t;
    int v = (i < n) ? g_cnt[i] : 0;
    int x = v;
    for (int o = 1; o < 32; o <<= 1) {
        int y = __shfl_up_sync(~0u, x, o);
        if (lane >= o) x += y;
    }
    if (lane == 31) wsum[wid] = x;
    __syncthreads();
    if (wid == 0) {
        int w = (lane < 16) ? wsum[lane] : 0;
        for (int o = 1; o < 16; o <<= 1) {
            int y = __shfl_up_sync(~0u, w, o);
            if (lane >= o) w += y;
        }
        if (lane < 16) wsum[lane] = w;
    }
    __syncthreads();
    int excl = x - v + (wid ? wsum[wid - 1] : 0);
    if (i < n) {
        int s = excl + sh_off;
        g_start[i] = s;
        g_cursor[i] = s;
    }
}

__global__ void k_fill(const int* __restrict__ src, const int* __restrict__ dst,
                       int e) {
    int i = blockIdx.x * blockDim.x + threadIdx.x;
    if (i < e) {
        int p = atomicAdd(&g_cursor[dst[i]], 1);
        g_esrc[p] = src[i];
    }
}

// ---------------------------------------------------------------------------
__device__ __forceinline__ unsigned pack_h2(float f0, float f1) {
    __half2 h = __floats2half2_rn(f0, f1);
    return *(unsigned*)&h;
}

// One-time: convert W into m16n8k16 fp16 B-fragment order.
__global__ void k_wprep(const float* __restrict__ W) {
    int i = blockIdx.x * blockDim.x + threadIdx.x;
    if (i >= 16 * 4 * 32) return;
    int lane = i & 31;
    int ktp = (i >> 5) & 3;
    int nt = i >> 7;
    int g = lane >> 2, t = lane & 3;
    int nc = nt * 8 + g;
    int k0 = ktp * 32 + 2 * t;
    uint4 o;
    o.x = pack_h2(W[(k0)      * F + nc], W[(k0 + 1)  * F + nc]);
    o.y = pack_h2(W[(k0 + 8)  * F + nc], W[(k0 + 9)  * F + nc]);
    o.z = pack_h2(W[(k0 + 16) * F + nc], W[(k0 + 17) * F + nc]);
    o.w = pack_h2(W[(k0 + 24) * F + nc], W[(k0 + 25) * F + nc]);
    g_wf16[i] = o;
}

// GEMM via HMMA fp16 (m16n8k16): g_h16 = (x @ W) * dinv[row], fp16 out.
// A frags loaded DIRECTLY from gmem (LDG.64, quad-covers 64B chunks) — no
// smem tile, no syncthreads, warps fully independent. B frags broadcast
// from g_wf16.
__global__ __launch_bounds__(256, 3) void k_gemm(const float* __restrict__ x,
                                                 int n) {
    const int tid = threadIdx.x;
    const int warp = tid >> 5, lane = tid & 31;
    const int g = lane >> 2, t = lane & 3;
    const int row0 = blockIdx.x * 128;

    // dinv for this block's rows (independent of the rest of this kernel)
    if (tid < 128 && row0 + tid < n)
        g_dinv[row0 + tid] = rsqrtf((float)(g_cnt[row0 + tid] + 1));

    const int rA = row0 + warp * 16 + g;
    const int rB = rA + 8;
    const float* xA = x + (size_t)((rA < n) ? rA : (n - 1)) * F;
    const float* xB = x + (size_t)((rB < n) ? rB : (n - 1)) * F;

    // A frags: 8 k-tiles x 4 half2 regs, loaded straight from gmem.
    unsigned a[8][4];
#pragma unroll
    for (int kt = 0; kt < 8; kt++) {
        int k0 = kt * 16 + 2 * t;
        float2 vA0 = *(const float2*)(xA + k0);
        float2 vB0 = *(const float2*)(xB + k0);
        float2 vA1 = *(const float2*)(xA + k0 + 8);
        float2 vB1 = *(const float2*)(xB + k0 + 8);
        a[kt][0] = pack_h2(vA0.x, vA0.y);
        a[kt][1] = pack_h2(vB0.x, vB0.y);
        a[kt][2] = pack_h2(vA1.x, vA1.y);
        a[kt][3] = pack_h2(vB1.x, vB1.y);
    }

    float sr  = (rA < n) ? rsqrtf((float)(g_cnt[rA] + 1)) : 0.f;
    float sr8 = (rB < n) ? rsqrtf((float)(g_cnt[rB] + 1)) : 0.f;

    const uint4* wf = g_wf16;
#pragma unroll 4
    for (int nt = 0; nt < 16; nt++) {
        float d0 = 0.f, d1 = 0.f, d2 = 0.f, d3 = 0.f;
#pragma unroll
        for (int ktp = 0; ktp < 4; ktp++) {
            uint4 bf = wf[(nt * 4 + ktp) * 32 + lane];
            asm volatile(
                "mma.sync.aligned.m16n8k16.row.col.f32.f16.f16.f32 "
                "{%0,%1,%2,%3}, {%4,%5,%6,%7}, {%8,%9}, {%0,%1,%2,%3};"
                : "+f"(d0), "+f"(d1), "+f"(d2), "+f"(d3)
                : "r"(a[2 * ktp][0]), "r"(a[2 * ktp][1]),
                  "r"(a[2 * ktp][2]), "r"(a[2 * ktp][3]),
                  "r"(bf.x), "r"(bf.y));
            asm volatile(
                "mma.sync.aligned.m16n8k16.row.col.f32.f16.f16.f32 "
                "{%0,%1,%2,%3}, {%4,%5,%6,%7}, {%8,%9}, {%0,%1,%2,%3};"
                : "+f"(d0), "+f"(d1), "+f"(d2), "+f"(d3)
                : "r"(a[2 * ktp + 1][0]), "r"(a[2 * ktp + 1][1]),
                  "r"(a[2 * ktp + 1][2]), "r"(a[2 * ktp + 1][3]),
                  "r"(bf.z), "r"(bf.w));
        }
        if (rA < n)
            g_h16[(size_t)rA * 64 + nt * 4 + t] =
                __floats2half2_rn(d0 * sr, d1 * sr);
        if (rB < n)
            g_h16[(size_t)rB * 64 + nt * 4 + t] =
                __floats2half2_rn(d2 * sr8, d3 * sr8);
    }
}

// ---------------------------------------------------------------------------
// Aggregate: one warp per dst node; uint2/lane fp16 gathers (256B rows),
// fp32 accumulation, 8 independent gathers in flight per iteration.
__global__ __launch_bounds__(256) void k_agg(const float* __restrict__ bias,
                                             float* __restrict__ out, int n) {
    int node = blockIdx.x * 8 + (threadIdx.x >> 5);
    if (node >= n) return;
    int lane = threadIdx.x & 31;

    const uint2* h = (const uint2*)g_h16;  // 4 halfs / lane / row
    float dd = g_dinv[node];

    float4 acc;
    {
        uint2 sv = h[(size_t)node * 32 + lane];  // self-loop message
        float2 f0 = __half22float2(*(__half2*)&sv.x);
        float2 f1 = __half22float2(*(__half2*)&sv.y);
        acc.x = f0.x; acc.y = f0.y; acc.z = f1.x; acc.w = f1.y;
    }

    int j = g_start[node];
    int end = j + g_cnt[node];

    for (; j + 7 < end; j += 8) {
        int s0 = g_esrc[j],     s1 = g_esrc[j + 1];
        int s2 = g_esrc[j + 2], s3 = g_esrc[j + 3];
        int s4 = g_esrc[j + 4], s5 = g_esrc[j + 5];
        int s6 = g_esrc[j + 6], s7 = g_esrc[j + 7];
        uint2 v0 = h[(size_t)s0 * 32 + lane];
        uint2 v1 = h[(size_t)s1 * 32 + lane];
        uint2 v2 = h[(size_t)s2 * 32 + lane];
        uint2 v3 = h[(size_t)s3 * 32 + lane];
        uint2 v4 = h[(size_t)s4 * 32 + lane];
        uint2 v5 = h[(size_t)s5 * 32 + lane];
        uint2 v6 = h[(size_t)s6 * 32 + lane];
        uint2 v7 = h[(size_t)s7 * 32 + lane];
#pragma unroll
        for (int k = 0; k < 8; k++) {
            uint2 v = (k == 0) ? v0 : (k == 1) ? v1 : (k == 2) ? v2 :
                      (k == 3) ? v3 : (k == 4) ? v4 : (k == 5) ? v5 :
                      (k == 6) ? v6 : v7;
            float2 f0 = __half22float2(*(__half2*)&v.x);
            float2 f1 = __half22float2(*(__half2*)&v.y);
            acc.x += f0.x; acc.y += f0.y; acc.z += f1.x; acc.w += f1.y;
        }
    }
    for (; j + 3 < end; j += 4) {
        int s0 = g_esrc[j],     s1 = g_esrc[j + 1];
        int s2 = g_esrc[j + 2], s3 = g_esrc[j + 3];
        uint2 v0 = h[(size_t)s0 * 32 + lane];
        uint2 v1 = h[(size_t)s1 * 32 + lane];
        uint2 v2 = h[(size_t)s2 * 32 + lane];
        uint2 v3 = h[(size_t)s3 * 32 + lane];
#pragma unroll
        for (int k = 0; k < 4; k++) {
            uint2 v = (k == 0) ? v0 : (k == 1) ? v1 : (k == 2) ? v2 : v3;
            float2 f0 = __half22float2(*(__half2*)&v.x);
            float2 f1 = __half22float2(*(__half2*)&v.y);
            acc.x += f0.x; acc.y += f0.y; acc.z += f1.x; acc.w += f1.y;
        }
    }
    for (; j < end; j++) {
        int s = g_esrc[j];
        uint2 v = h[(size_t)s * 32 + lane];
        float2 f0 = __half22float2(*(__half2*)&v.x);
        float2 f1 = __half22float2(*(__half2*)&v.y);
        acc.x += f0.x; acc.y += f0.y; acc.z += f1.x; acc.w += f1.y;
    }

    float4 bv = ((const float4*)bias)[lane];
    float4 o;
    o.x = acc.x * dd + bv.x;
    o.y = acc.y * dd + bv.y;
    o.z = acc.z * dd + bv.z;
    o.w = acc.w * dd + bv.w;
    ((float4*)out)[(size_t)node * 32 + lane] = o;
}

// ---------------------------------------------------------------------------
// Launch DAG (R12/R14 structure):
//   zero -> hist -> [A: scan1 -> scan3 -> fill]   (edge chain, hidden)
//                   [B: wprep -> gemm]            (dense chain, side stream)
//   join(A, B) -> agg
extern "C" void kernel_launch(void* const* d_in, const int* in_sizes, int n_in,
                              void* d_out, int out_size) {
    const float* x  = (const float*)d_in[0];
    const int*   ei = (const int*)d_in[1];
    const float* W  = (const float*)d_in[3];
    const float* b  = (const float*)d_in[4];
    float* out = (float*)d_out;

    int n = in_sizes[0] / F;
    int e = in_sizes[1] / 2;
    const int* src = ei;
    const int* dst = ei + e;

    int nblk = (n + SCAN_CHUNK - 1) / SCAN_CHUNK;

    // One-time host-side setup on the (uncaptured) correctness call.
    static cudaStream_t s2 = nullptr;
    static cudaEvent_t evHist = nullptr, evGemm = nullptr;
    if (s2 == nullptr) {
        cudaStreamCreateWithFlags(&s2, cudaStreamNonBlocking);
        cudaEventCreateWithFlags(&evHist, cudaEventDisableTiming);
        cudaEventCreateWithFlags(&evGemm, cudaEventDisableTiming);
    }

    k_zero <<<(n + 255) / 256, 256>>>(n);
    k_hist <<<(e + 255) / 256, 256>>>(dst, e);
    cudaEventRecord(evHist, 0);

    // dense chain on side stream (waits for hist: gemm reads g_cnt for dinv)
    cudaStreamWaitEvent(s2, evHist, 0);
    k_wprep<<<8, 256, 0, s2>>>(W);
    k_gemm <<<(n + 127) / 128, 256, 0, s2>>>(x, n);
    cudaEventRecord(evGemm, s2);

    // edge chain on main stream (overlaps with gemm)
    k_scan1<<<nblk, SCAN_CHUNK>>>(n);
    k_scan3<<<nblk, SCAN_CHUNK>>>(n, nblk);
    k_fill <<<(e + 255) / 256, 256>>>(src, dst, e);

    // join
    cudaStreamWaitEvent(0, evGemm, 0);
    k_agg  <<<(n + 7) / 8, 256>>>(b, out, n);
}